// round 4
// baseline (speedup 1.0000x reference)
#include <cuda_runtime.h>
#include <math.h>

// Problem dims
#define B 32
#define S 256
#define EHID 768
#define DHID 128
#define EMBD 200
#define VOC 32000
#define TT 96
#define NSTEP 95
#define KFC 1096    // DHID + EHID + EMBD
#define KLSTM 968   // EMBD + EHID

// Scratch (static device globals: allowed; no runtime allocation)
__device__ float g_fcwt[(size_t)KFC * VOC];   // fc_W transposed: [k][v], ~140MB
__device__ float g_enc_proj[B * S * DHID];    // 4MB, step-invariant attention term
__device__ float g_xcatT[KFC * B];            // FC input, transposed [k][b]
__device__ float g_h[B * DHID];
__device__ float g_c[B * DHID];

__device__ __forceinline__ float sigf(float x) { return 1.0f / (1.0f + expf(-x)); }

// ---------------------------------------------------------------------------
// Init: zero h, c, and outputs[:, 0, :]
// ---------------------------------------------------------------------------
__global__ void k_init(float* __restrict__ outp) {
    int i = blockIdx.x * blockDim.x + threadIdx.x;
    if (i < B * VOC) {
        int b = i / VOC, v = i % VOC;
        outp[(size_t)b * TT * VOC + v] = 0.0f;   // outputs[b][0][v] = 0
    }
    if (i < B * DHID) { g_h[i] = 0.0f; g_c[i] = 0.0f; }
}

// ---------------------------------------------------------------------------
// Transpose fc_W [VOC][KFC] -> g_fcwt [KFC][VOC] (once)
// ---------------------------------------------------------------------------
__global__ void k_transpose(const float* __restrict__ W) {
    __shared__ float tile[32][33];
    int tx = threadIdx.x, ty = threadIdx.y;          // 32 x 8
    int v0 = blockIdx.x * 32, k0 = blockIdx.y * 32;
    for (int r = ty; r < 32; r += 8) {
        int k = k0 + tx;
        tile[r][tx] = (k < KFC) ? W[(size_t)(v0 + r) * KFC + k] : 0.0f;
    }
    __syncthreads();
    for (int r = ty; r < 32; r += 8) {
        int k = k0 + r;
        if (k < KFC) g_fcwt[(size_t)k * VOC + v0 + tx] = tile[tx][r];
    }
}

// ---------------------------------------------------------------------------
// enc_proj[b,s,j] = attn_b[j] + sum_k enc[b,s,k] * attn_W[128+k][j]   (once)
// block: 32 rows (b*s) x 128 cols. 128 threads, 32 accumulators each.
// ---------------------------------------------------------------------------
__global__ void __launch_bounds__(128) k_encproj(const float* __restrict__ enc,
                                                 const float* __restrict__ attn_W,
                                                 const float* __restrict__ attn_b) {
    __shared__ __align__(16) float es[32 * 8];    // 32 rows x 8 k-chunk
    int j = threadIdx.x;
    int row0 = blockIdx.x * 32;
    float acc[32];
    float bj = attn_b[j];
#pragma unroll
    for (int r = 0; r < 32; r++) acc[r] = bj;
    const float* Wenc = attn_W + DHID * DHID;     // rows 128..895

    for (int k0 = 0; k0 < EHID; k0 += 8) {
        __syncthreads();
        int i0 = j;
        es[i0] = enc[(size_t)(row0 + (i0 >> 3)) * EHID + k0 + (i0 & 7)];
        int i1 = j + 128;
        es[i1] = enc[(size_t)(row0 + (i1 >> 3)) * EHID + k0 + (i1 & 7)];
        __syncthreads();
        float w[8];
#pragma unroll
        for (int kk = 0; kk < 8; kk++) w[kk] = Wenc[(size_t)(k0 + kk) * DHID + j];
#pragma unroll
        for (int r = 0; r < 32; r++) {
            const float4* e4 = (const float4*)(es + r * 8);
            float4 e0 = e4[0], e1 = e4[1];
            acc[r] = fmaf(e0.x, w[0], acc[r]); acc[r] = fmaf(e0.y, w[1], acc[r]);
            acc[r] = fmaf(e0.z, w[2], acc[r]); acc[r] = fmaf(e0.w, w[3], acc[r]);
            acc[r] = fmaf(e1.x, w[4], acc[r]); acc[r] = fmaf(e1.y, w[5], acc[r]);
            acc[r] = fmaf(e1.z, w[6], acc[r]); acc[r] = fmaf(e1.w, w[7], acc[r]);
        }
    }
#pragma unroll
    for (int r = 0; r < 32; r++)
        g_enc_proj[(size_t)(row0 + r) * DHID + j] = acc[r];
}

// ---------------------------------------------------------------------------
// Per-step: attention + softmax + context + LSTM (fused). grid=B, 512 threads.
// ---------------------------------------------------------------------------
__global__ void __launch_bounds__(512) k_step(
    const float* __restrict__ enc, const int* __restrict__ trg,
    const float* __restrict__ embt, const float* __restrict__ attn_W,
    const float* __restrict__ attn_v, const float* __restrict__ W_ih,
    const float* __restrict__ W_hh, const float* __restrict__ b_ih,
    const float* __restrict__ b_hh, int t)
{
    int b = blockIdx.x, tid = threadIdx.x;
    __shared__ __align__(16) float sh_h[DHID];
    __shared__ float sh_hp[DHID];
    __shared__ float sh_v[DHID];
    __shared__ float sh_a[S];
    __shared__ float sh_red[512];
    __shared__ __align__(16) float sh_xl[KLSTM];
    __shared__ float sh_gates[512];

    if (tid < DHID) { sh_h[tid] = g_h[b * DHID + tid]; sh_v[tid] = attn_v[tid]; }
    __syncthreads();

    // h projection: hp[j] = sum_k h[k] * attn_W[k][j]
    if (tid < DHID) {
        float acc = 0.0f;
#pragma unroll 8
        for (int k = 0; k < DHID; k++)
            acc = fmaf(sh_h[k], attn_W[k * DHID + tid], acc);
        sh_hp[tid] = acc;
    }
    __syncthreads();

    // scores: score[s] = sum_j tanh(enc_proj[b,s,j] + hp[j]) * v[j], split over 2 j-halves
    {
        int s = tid & (S - 1);
        int j0 = (tid >> 8) * 64;
        const float* ep = g_enc_proj + ((size_t)b * S + s) * DHID + j0;
        float acc = 0.0f;
#pragma unroll 4
        for (int jj = 0; jj < 64; jj++)
            acc = fmaf(tanhf(ep[jj] + sh_hp[j0 + jj]), sh_v[j0 + jj], acc);
        sh_red[tid] = acc;
    }
    __syncthreads();
    if (tid < S) sh_a[tid] = sh_red[tid] + sh_red[tid + S];
    __syncthreads();

    // softmax over S=256 (max-subtract, matching jax.nn.softmax)
    if (tid < S) sh_red[tid] = sh_a[tid];
    __syncthreads();
    for (int off = S / 2; off > 0; off >>= 1) {
        if (tid < off) sh_red[tid] = fmaxf(sh_red[tid], sh_red[tid + off]);
        __syncthreads();
    }
    float mx = sh_red[0];
    __syncthreads();
    if (tid < S) { float e = expf(sh_a[tid] - mx); sh_a[tid] = e; sh_red[tid] = e; }
    __syncthreads();
    for (int off = S / 2; off > 0; off >>= 1) {
        if (tid < off) sh_red[tid] += sh_red[tid + off];
        __syncthreads();
    }
    float inv = 1.0f / sh_red[0];
    if (tid < S) sh_a[tid] *= inv;
    __syncthreads();

    // context: weighted[d] = sum_s a[s] * enc[b,s,d]
    const float* encb = enc + (size_t)b * S * EHID;
    for (int d = tid; d < EHID; d += 512) {
        float acc = 0.0f;
#pragma unroll 8
        for (int s = 0; s < S; s++)
            acc = fmaf(sh_a[s], encb[(size_t)s * EHID + d], acc);
        sh_xl[EMBD + d] = acc;                       // LSTM x = [emb, weighted]
        g_xcatT[(DHID + d) * B + b] = acc;           // FC x = [h, weighted, emb]
    }
    // embedding gather
    int tok = trg[b * TT + t];
    if (tid < EMBD) {
        float ev = embt[(size_t)tok * EMBD + tid];
        sh_xl[tid] = ev;
        g_xcatT[(DHID + EHID + tid) * B + b] = ev;
    }
    __syncthreads();

    // LSTM gates: gates[g] = b_ih[g]+b_hh[g] + x.W_ih[g,:] + h.W_hh[g,:]
    {
        int g = tid;
        float acc = b_ih[g] + b_hh[g];
        const float4* w4 = (const float4*)(W_ih + (size_t)g * KLSTM);
        const float4* x4 = (const float4*)sh_xl;
#pragma unroll 2
        for (int k = 0; k < KLSTM / 4; k++) {
            float4 w = w4[k]; float4 x = x4[k];
            acc = fmaf(w.x, x.x, acc); acc = fmaf(w.y, x.y, acc);
            acc = fmaf(w.z, x.z, acc); acc = fmaf(w.w, x.w, acc);
        }
        const float4* wh4 = (const float4*)(W_hh + (size_t)g * DHID);
        const float4* h4 = (const float4*)sh_h;
#pragma unroll
        for (int k = 0; k < DHID / 4; k++) {
            float4 w = wh4[k]; float4 x = h4[k];
            acc = fmaf(w.x, x.x, acc); acc = fmaf(w.y, x.y, acc);
            acc = fmaf(w.z, x.z, acc); acc = fmaf(w.w, x.w, acc);
        }
        sh_gates[g] = acc;
    }
    __syncthreads();

    // cell/hidden update (pytorch gate order i,f,g,o)
    if (tid < DHID) {
        float gi = sh_gates[tid];
        float gf = sh_gates[DHID + tid];
        float gg = sh_gates[2 * DHID + tid];
        float go = sh_gates[3 * DHID + tid];
        float c = g_c[b * DHID + tid];
        c = sigf(gf) * c + sigf(gi) * tanhf(gg);
        float h = sigf(go) * tanhf(c);
        g_c[b * DHID + tid] = c;
        g_h[b * DHID + tid] = h;
        g_xcatT[tid * B + b] = h;                    // FC x[0..127] = new h
    }
}

// ---------------------------------------------------------------------------
// Per-step FC: pred[b][v] = fc_b[v] + sum_k xcat[b][k] * fc_wt[k][v]
// grid = VOC/32 = 1000 blocks, 128 threads. lane -> v, warp -> 8 batches.
// Per k per thread: 1 streaming LDG (w) + 2 uniform LDG.128 (x) + 8 FFMA.
// ---------------------------------------------------------------------------
__global__ void __launch_bounds__(128) k_fc(const float* __restrict__ fc_b,
                                            float* __restrict__ outp, int t) {
    int lane = threadIdx.x & 31;
    int wrp  = threadIdx.x >> 5;
    int v  = blockIdx.x * 32 + lane;
    int b0 = wrp * 8;
    const float* wp = g_fcwt + v;
    const float4* xp = (const float4*)(g_xcatT + b0);
    float4 a0 = make_float4(0.f, 0.f, 0.f, 0.f);
    float4 a1 = make_float4(0.f, 0.f, 0.f, 0.f);
#pragma unroll 4
    for (int k = 0; k < KFC; k++) {
        float w  = __ldcs(wp + (size_t)k * VOC);   // streaming: don't thrash L1
        float4 xa = __ldg(xp + k * 8);
        float4 xb = __ldg(xp + k * 8 + 1);
        a0.x = fmaf(w, xa.x, a0.x); a0.y = fmaf(w, xa.y, a0.y);
        a0.z = fmaf(w, xa.z, a0.z); a0.w = fmaf(w, xa.w, a0.w);
        a1.x = fmaf(w, xb.x, a1.x); a1.y = fmaf(w, xb.y, a1.y);
        a1.z = fmaf(w, xb.z, a1.z); a1.w = fmaf(w, xb.w, a1.w);
    }
    float bias = fc_b[v];
    float* o = outp + (size_t)(t + 1) * VOC + v;   // outputs[b][t+1][v]
    const size_t bs = (size_t)TT * VOC;
    o[(size_t)(b0 + 0) * bs] = a0.x + bias;
    o[(size_t)(b0 + 1) * bs] = a0.y + bias;
    o[(size_t)(b0 + 2) * bs] = a0.z + bias;
    o[(size_t)(b0 + 3) * bs] = a0.w + bias;
    o[(size_t)(b0 + 4) * bs] = a1.x + bias;
    o[(size_t)(b0 + 5) * bs] = a1.y + bias;
    o[(size_t)(b0 + 6) * bs] = a1.z + bias;
    o[(size_t)(b0 + 7) * bs] = a1.w + bias;
}

// ---------------------------------------------------------------------------
// Epilogue: argmax over V per (b,t) row (first-index on ties -> zeros row = 0)
// ---------------------------------------------------------------------------
__global__ void __launch_bounds__(256) k_argmax(const float* __restrict__ outp,
                                                float* __restrict__ tokout) {
    int row = blockIdx.x;                        // b*TT + t
    const float* p = outp + (size_t)row * VOC;
    int tid = threadIdx.x;
    float best = -1e30f;
    int bi = VOC;
    for (int i = tid; i < VOC; i += 256) {
        float vv = p[i];
        if (vv > best || (vv == best && i < bi)) { best = vv; bi = i; }
    }
    __shared__ float sv[256];
    __shared__ int si[256];
    sv[tid] = best; si[tid] = bi;
    __syncthreads();
    for (int off = 128; off > 0; off >>= 1) {
        if (tid < off) {
            float ov = sv[tid + off]; int oi = si[tid + off];
            if (ov > sv[tid] || (ov == sv[tid] && oi < si[tid])) { sv[tid] = ov; si[tid] = oi; }
        }
        __syncthreads();
    }
    if (tid == 0) tokout[row] = (float)si[0];
}

// ---------------------------------------------------------------------------
extern "C" void kernel_launch(void* const* d_in, const int* in_sizes, int n_in,
                              void* d_out, int out_size) {
    const float* enc    = (const float*)d_in[0];
    const int*   trg    = (const int*)d_in[1];
    const float* embt   = (const float*)d_in[2];
    const float* attn_W = (const float*)d_in[3];
    const float* attn_b = (const float*)d_in[4];
    const float* attn_v = (const float*)d_in[5];
    const float* W_ih   = (const float*)d_in[6];
    const float* W_hh   = (const float*)d_in[7];
    const float* b_ih   = (const float*)d_in[8];
    const float* b_hh   = (const float*)d_in[9];
    const float* fc_W   = (const float*)d_in[10];
    const float* fc_b   = (const float*)d_in[11];
    float* outp = (float*)d_out;
    (void)in_sizes; (void)n_in;

    k_init<<<(B * VOC + 255) / 256, 256>>>(outp);
    k_transpose<<<dim3(VOC / 32, (KFC + 31) / 32), dim3(32, 8)>>>(fc_W);
    k_encproj<<<(B * S) / 32, 128>>>(enc, attn_W, attn_b);

    for (int t = 0; t < NSTEP; t++) {
        k_step<<<B, 512>>>(enc, trg, embt, attn_W, attn_v,
                           W_ih, W_hh, b_ih, b_hh, t);
        k_fc<<<VOC / 32, 128>>>(fc_b, outp, t);
    }

    // predicted_tokens (if the output buffer includes them after the logits)
    long long need = (long long)B * TT * VOC + (long long)B * TT;
    if ((long long)out_size >= need) {
        k_argmax<<<B * TT, 256>>>(outp, outp + (size_t)B * TT * VOC);
    }
}